// round 15
// baseline (speedup 1.0000x reference)
#include <cuda_runtime.h>
#include <cuda_fp16.h>
#include <cstdint>

#define D 128
#define NMAX 100000
#define EMAX 3200000

#define SCAN_CHUNK 2048
#define MAX_CHUNKS ((NMAX + SCAN_CHUNK - 1) / SCAN_CHUNK)   // 49

__device__ float g_m1[(size_t)NMAX * D];
__device__ int   g_counts[NMAX];          // zero-init at load; re-zeroed by scan kernel
__device__ int   g_row_start[NMAX + 1];
__device__ int   g_cursor[NMAX];
__device__ int2  g_edges[EMAX];           // .x = source node (col), .y = val bits
__device__ uint2 g_ehalf[(size_t)NMAX * 32];
// decoupled-lookback state (flags re-zeroed by scatter kernel each iteration)
__device__ int           g_blk_agg[64];
__device__ int           g_blk_inc[64];
__device__ volatile int  g_blk_flag[64];  // 0=invalid, 1=agg ready, 2=inclusive ready

// ---------------------------------------------------------------------------
// JAX threefry2x32, key=(0,42); confirmed: ctr=(hi=0, lo=i), bits = x0.
// ---------------------------------------------------------------------------
__device__ __forceinline__ unsigned int threefry_x0_k42(unsigned int ctr_lo) {
    unsigned int x0 = 0u;
    unsigned int x1 = ctr_lo;
    const unsigned int ks1 = 42u;
    const unsigned int ks2 = 42u ^ 0x1BD11BDAu;
    x1 += ks1;
#define TF_ROUND(r) { x0 += x1; x1 = __funnelshift_l(x1, x1, (r)); x1 ^= x0; }
    TF_ROUND(13) TF_ROUND(15) TF_ROUND(26) TF_ROUND(6)
    x0 += ks1; x1 += ks2 + 1u;
    TF_ROUND(17) TF_ROUND(29) TF_ROUND(16) TF_ROUND(24)
    x0 += ks2; x1 += 0u + 2u;
    TF_ROUND(13) TF_ROUND(15) TF_ROUND(26) TF_ROUND(6)
    x0 += 0u;  x1 += ks1 + 3u;
    TF_ROUND(17) TF_ROUND(29) TF_ROUND(16) TF_ROUND(24)
    x0 += ks1; x1 += ks2 + 4u;
    TF_ROUND(13) TF_ROUND(15) TF_ROUND(26) TF_ROUND(6)
    x0 += ks2;
#undef TF_ROUND
    return x0;
}

__device__ __forceinline__ float drop_one(float v, unsigned int i) {
    unsigned int bits = threefry_x0_k42(i);
    float u = __uint_as_float(0x3f800000u | (bits >> 9)) - 1.0f;
    return (u < 0.9f) ? (v * (1.0f / 0.9f)) : 0.0f;
}

// ---------------------------------------------------------------------------
// packed fp32x2 helpers
// ---------------------------------------------------------------------------
__device__ __forceinline__ unsigned long long pack_dup(float x) {
    unsigned long long r;
    asm("mov.b64 %0, {%1, %1};" : "=l"(r) : "f"(x));
    return r;
}
__device__ __forceinline__ void ffma2(unsigned long long& d,
                                      unsigned long long a,
                                      unsigned long long b) {
    asm("fma.rn.f32x2 %0, %1, %2, %0;" : "+l"(d) : "l"(a), "l"(b));
}
__device__ __forceinline__ float2 unpack2(unsigned long long p) {
    float lo, hi;
    asm("mov.b64 {%0, %1}, %2;" : "=f"(lo), "=f"(hi) : "l"(p));
    return make_float2(lo, hi);
}

// ---------------------------------------------------------------------------
// Kernel 0: fused fp16-embed prep + row histogram.
// counts[] is guaranteed zero on entry: zero-init at module load for the first
// call; re-zeroed by scan_lookback_kernel at the end of each iteration.
// ---------------------------------------------------------------------------
__global__ void prep_hist_kernel(const float* __restrict__ embed_w,
                                 const int* __restrict__ row, int N, int E) {
    int idx = blockIdx.x * blockDim.x + threadIdx.x;
    // fp16 conversion over N*32 float4s
    if (idx < N * 32) {
        float4 f = reinterpret_cast<const float4*>(embed_w)[idx];
        __half2 a = __floats2half2_rn(f.x, f.y);
        __half2 b = __floats2half2_rn(f.z, f.w);
        uint2 u;
        u.x = *reinterpret_cast<uint32_t*>(&a);
        u.y = *reinterpret_cast<uint32_t*>(&b);
        g_ehalf[idx] = u;
    }
    // histogram, 4 edges per thread
    int e0 = idx * 4;
    if (e0 + 3 < E) {
        int4 r4 = reinterpret_cast<const int4*>(row)[idx];
        atomicAdd(&g_counts[r4.x], 1);
        atomicAdd(&g_counts[r4.y], 1);
        atomicAdd(&g_counts[r4.z], 1);
        atomicAdd(&g_counts[r4.w], 1);
    } else if (e0 < E) {
        for (int e = e0; e < E; e++) atomicAdd(&g_counts[row[e]], 1);
    }
}

// ---------------------------------------------------------------------------
// Kernel 1: single-pass decoupled-lookback scan over counts ->
// row_start/cursor (exclusive prefix), re-zeros counts, sets row_start[N]=E.
// 49 blocks x 1024 threads, 2048 counts per block. Flags zeroed on entry
// (load-time init / scatter kernel reset).
// ---------------------------------------------------------------------------
__global__ __launch_bounds__(1024)
void scan_lookback_kernel(int N, int E) {
    __shared__ int sh[1024];
    __shared__ int sh_prefix;
    const int b = blockIdx.x, t = threadIdx.x;
    const int i0 = b * SCAN_CHUNK + 2 * t;

    int c0 = (i0 < N)     ? g_counts[i0]     : 0;
    int c1 = (i0 + 1 < N) ? g_counts[i0 + 1] : 0;
    int pair = c0 + c1;
    sh[t] = pair;
    __syncthreads();
    // inclusive Hillis-Steele over 1024 pair-sums
    for (int off = 1; off < 1024; off <<= 1) {
        int v = (t >= off) ? sh[t - off] : 0;
        __syncthreads();
        sh[t] += v;
        __syncthreads();
    }
    int chunk_total = sh[1023];
    int incl_pair   = sh[t];

    if (t == 0) {
        g_blk_agg[b] = chunk_total;
        __threadfence();
        g_blk_flag[b] = 1;
        // lookback
        int running = 0;
        for (int j = b - 1; j >= 0; j--) {
            int f;
            do { f = g_blk_flag[j]; } while (f == 0);
            __threadfence();
            if (f == 2) { running += g_blk_inc[j]; break; }
            running += g_blk_agg[j];
        }
        g_blk_inc[b] = running + chunk_total;
        __threadfence();
        g_blk_flag[b] = 2;
        sh_prefix = running;
    }
    __syncthreads();
    int excl = incl_pair - pair + sh_prefix;

    if (i0 < N)     { g_row_start[i0]     = excl;      g_cursor[i0]     = excl;      g_counts[i0]     = 0; }
    if (i0 + 1 < N) { g_row_start[i0 + 1] = excl + c0; g_cursor[i0 + 1] = excl + c0; g_counts[i0 + 1] = 0; }
    if (i0 == N - 1 || i0 + 1 == N - 1) g_row_start[N] = E;
}

// ---------------------------------------------------------------------------
// Kernel 2: scatter edges into CSR order; also resets lookback flags for the
// next graph replay (runs strictly after scan completes).
// ---------------------------------------------------------------------------
__global__ void scatter_kernel(const int* __restrict__ row,
                               const int* __restrict__ col,
                               const float* __restrict__ vals, int E) {
    if (blockIdx.x == 0 && threadIdx.x < 64) g_blk_flag[threadIdx.x] = 0;
    int e = blockIdx.x * blockDim.x + threadIdx.x;
    if (e >= E) return;
    int r = row[e];
    int pos = atomicAdd(&g_cursor[r], 1);
    g_edges[pos] = make_int2(col[e], __float_as_int(vals[e]));
}

// ---------------------------------------------------------------------------
// Kernel 3 (PROFILED at ncu index 3): fused CSR SpMM + residual + dropout +
// e-copy. MLP-8 batched fp16 gathers.
// ---------------------------------------------------------------------------
__global__ __launch_bounds__(256)
void spmm_csr_kernel(const float* __restrict__ embed_w,
                     float* __restrict__ out, int N) {
    int r = (blockIdx.x * blockDim.x + threadIdx.x) >> 5;
    if (r >= N) return;
    int lane = threadIdx.x & 31;

    float4 acc = reinterpret_cast<const float4*>(embed_w)[(size_t)r * 32 + lane];
    reinterpret_cast<float4*>(out)[(size_t)r * 64 + lane] = acc;

    int start = g_row_start[r];
    int end   = g_row_start[r + 1];

    for (int base = start; base < end; base += 32) {
        int j = base + lane;
        int  c = 0;
        float v = 0.0f;
        if (j < end) {
            int2 ed = g_edges[j];
            c = ed.x;
            v = __int_as_float(ed.y);
        }
        int m = min(32, end - base);
        int k = 0;
        for (; k + 8 <= m; k += 8) {
            uint2 hv[8];
            float vk[8];
#pragma unroll
            for (int u = 0; u < 8; u++) {
                int ck = __shfl_sync(0xFFFFFFFFu, c, k + u);
                vk[u]  = __shfl_sync(0xFFFFFFFFu, v, k + u);
                hv[u]  = g_ehalf[(size_t)ck * 32 + lane];
            }
#pragma unroll
            for (int u = 0; u < 8; u++) {
                float2 f01 = __half22float2(*reinterpret_cast<__half2*>(&hv[u].x));
                float2 f23 = __half22float2(*reinterpret_cast<__half2*>(&hv[u].y));
                acc.x += vk[u] * f01.x;
                acc.y += vk[u] * f01.y;
                acc.z += vk[u] * f23.x;
                acc.w += vk[u] * f23.y;
            }
        }
        for (; k < m; k++) {
            int   ck = __shfl_sync(0xFFFFFFFFu, c, k);
            float vk = __shfl_sync(0xFFFFFFFFu, v, k);
            uint2 hv = g_ehalf[(size_t)ck * 32 + lane];
            float2 f01 = __half22float2(*reinterpret_cast<__half2*>(&hv.x));
            float2 f23 = __half22float2(*reinterpret_cast<__half2*>(&hv.y));
            acc.x += vk * f01.x;
            acc.y += vk * f01.y;
            acc.z += vk * f23.x;
            acc.w += vk * f23.y;
        }
    }

    unsigned int i0 = (unsigned int)r * 128u + (unsigned int)lane * 4u;
    acc.x = drop_one(acc.x, i0 + 0u);
    acc.y = drop_one(acc.y, i0 + 1u);
    acc.z = drop_one(acc.z, i0 + 2u);
    acc.w = drop_one(acc.w, i0 + 3u);

    reinterpret_cast<float4*>(g_m1)[(size_t)r * 32 + lane] = acc;
}

// ---------------------------------------------------------------------------
// Kernel 4: GEMM (FFMA2): out[:, 128:256] = leaky_relu(m1 @ W^T + b)
// ---------------------------------------------------------------------------
#define KPAD 132

__global__ __launch_bounds__(256, 2)
void gemm_kernel(const float* __restrict__ W,
                 const float* __restrict__ bias,
                 float* __restrict__ out, int N) {
    __shared__ float As[32 * KPAD];   // [k][row]
    __shared__ float Ws[32 * KPAD];   // [k][outcol]
    const int t  = threadIdx.x;
    const int tx = t & 15;
    const int ty = t >> 4;
    const int brow = blockIdx.x * 128;

    unsigned long long acc2[8][4];
#pragma unroll
    for (int u = 0; u < 8; u++)
#pragma unroll
        for (int v = 0; v < 4; v++) acc2[u][v] = 0ull;

#pragma unroll 1
    for (int kk = 0; kk < 4; kk++) {
        if (kk) __syncthreads();
#pragma unroll
        for (int i = 0; i < 4; i++) {
            int idx = t + i * 256;
            int r   = idx >> 3;
            int c4  = (idx & 7) * 4;
            int gr  = brow + r;
            float4 av = make_float4(0.f, 0.f, 0.f, 0.f);
            if (gr < N)
                av = *reinterpret_cast<const float4*>(g_m1 + (size_t)gr * D + kk * 32 + c4);
            As[(c4 + 0) * KPAD + r] = av.x;
            As[(c4 + 1) * KPAD + r] = av.y;
            As[(c4 + 2) * KPAD + r] = av.z;
            As[(c4 + 3) * KPAD + r] = av.w;
            float4 wv = *reinterpret_cast<const float4*>(W + (size_t)r * D + kk * 32 + c4);
            Ws[(c4 + 0) * KPAD + r] = wv.x;
            Ws[(c4 + 1) * KPAD + r] = wv.y;
            Ws[(c4 + 2) * KPAD + r] = wv.z;
            Ws[(c4 + 3) * KPAD + r] = wv.w;
        }
        __syncthreads();
#pragma unroll
        for (int k = 0; k < 32; k++) {
            float4 aLo = *reinterpret_cast<const float4*>(&As[k * KPAD + ty * 4]);
            float4 aHi = *reinterpret_cast<const float4*>(&As[k * KPAD + ty * 4 + 64]);
            const unsigned long long* wp =
                reinterpret_cast<const unsigned long long*>(&Ws[k * KPAD]);
            unsigned long long w0 = wp[tx * 2];
            unsigned long long w1 = wp[tx * 2 + 1];
            unsigned long long w2 = wp[tx * 2 + 32];
            unsigned long long w3 = wp[tx * 2 + 33];
            float a[8] = {aLo.x, aLo.y, aLo.z, aLo.w, aHi.x, aHi.y, aHi.z, aHi.w};
#pragma unroll
            for (int u = 0; u < 8; u++) {
                unsigned long long aa = pack_dup(a[u]);
                ffma2(acc2[u][0], aa, w0);
                ffma2(acc2[u][1], aa, w1);
                ffma2(acc2[u][2], aa, w2);
                ffma2(acc2[u][3], aa, w3);
            }
        }
    }

    float bv[8];
#pragma unroll
    for (int v = 0; v < 4; v++) {
        bv[v]     = bias[tx * 4 + v];
        bv[v + 4] = bias[tx * 4 + 64 + v];
    }

#pragma unroll
    for (int u = 0; u < 8; u++) {
        int gr = brow + ((u < 4) ? (ty * 4 + u) : (ty * 4 + 64 + u - 4));
        if (gr >= N) continue;
        float* o = out + (size_t)gr * 256 + 128;
        float2 p0 = unpack2(acc2[u][0]);
        float2 p1 = unpack2(acc2[u][1]);
        float2 p2 = unpack2(acc2[u][2]);
        float2 p3 = unpack2(acc2[u][3]);
        float y[8] = {p0.x, p0.y, p1.x, p1.y, p2.x, p2.y, p3.x, p3.y};
#pragma unroll
        for (int v = 0; v < 8; v++) {
            float z = y[v] + bv[v];
            y[v] = (z >= 0.0f) ? z : 0.2f * z;
        }
        *reinterpret_cast<float4*>(o + tx * 4)      = make_float4(y[0], y[1], y[2], y[3]);
        *reinterpret_cast<float4*>(o + tx * 4 + 64) = make_float4(y[4], y[5], y[6], y[7]);
    }
}

// ---------------------------------------------------------------------------
extern "C" void kernel_launch(void* const* d_in, const int* in_sizes, int n_in,
                              void* d_out, int out_size) {
    const int*   row     = (const int*)d_in[1];
    const int*   col     = (const int*)d_in[2];
    const float* vals    = (const float*)d_in[3];
    const float* embed_w = (const float*)d_in[4];
    const float* fc_w    = (const float*)d_in[5];
    const float* fc_b    = (const float*)d_in[6];
    float* out = (float*)d_out;

    const int N = in_sizes[0];
    const int E = in_sizes[1];
    const int nchunks = (N + SCAN_CHUNK - 1) / SCAN_CHUNK;   // 49

    int prep_threads = N * 32;                 // covers both N*32 and E/4 ranges
    if ((E + 3) / 4 > prep_threads) prep_threads = (E + 3) / 4;

    // 0: fused fp16 prep + histogram
    prep_hist_kernel<<<(prep_threads + 255) / 256, 256>>>(embed_w, row, N, E);
    // 1: single-pass scan (also re-zeros counts)
    scan_lookback_kernel<<<nchunks, 1024>>>(N, E);
    // 2: scatter (also resets lookback flags)
    scatter_kernel<<<(E + 255) / 256, 256>>>(row, col, vals, E);
    // 3: fused SpMM + residual + dropout + e-copy  <-- profiled launch index
    spmm_csr_kernel<<<(N * 32 + 255) / 256, 256>>>(embed_w, out, N);
    // 4: GEMM
    gemm_kernel<<<(N + 127) / 128, 256>>>(fc_w, fc_b, out, N);
}

// round 16
// speedup vs baseline: 1.0881x; 1.0881x over previous
#include <cuda_runtime.h>
#include <cuda_fp16.h>
#include <cstdint>

#define D 128
#define NMAX 100000
#define EMAX 3200000

#define SCAN_CHUNK 2048
#define MAX_CHUNKS ((NMAX + SCAN_CHUNK - 1) / SCAN_CHUNK)   // 49

__device__ float g_m1[(size_t)NMAX * D];
__device__ int   g_counts[NMAX];          // zero-init at load; re-zeroed by scan kernel
__device__ int   g_row_start[NMAX + 1];
__device__ int   g_cursor[NMAX];
__device__ int2  g_edges[EMAX + 8];       // .x = col, .y = half2(v,v); +8 pad for batch overread
__device__ uint2 g_ehalf[(size_t)NMAX * 32];
// decoupled-lookback state (flags re-zeroed by scatter kernel each iteration)
__device__ int           g_blk_agg[64];
__device__ int           g_blk_inc[64];
__device__ volatile int  g_blk_flag[64];

// ---------------------------------------------------------------------------
// JAX threefry2x32, key=(0,42); confirmed: ctr=(hi=0, lo=i), bits = x0.
// ---------------------------------------------------------------------------
__device__ __forceinline__ unsigned int threefry_x0_k42(unsigned int ctr_lo) {
    unsigned int x0 = 0u;
    unsigned int x1 = ctr_lo;
    const unsigned int ks1 = 42u;
    const unsigned int ks2 = 42u ^ 0x1BD11BDAu;
    x1 += ks1;
#define TF_ROUND(r) { x0 += x1; x1 = __funnelshift_l(x1, x1, (r)); x1 ^= x0; }
    TF_ROUND(13) TF_ROUND(15) TF_ROUND(26) TF_ROUND(6)
    x0 += ks1; x1 += ks2 + 1u;
    TF_ROUND(17) TF_ROUND(29) TF_ROUND(16) TF_ROUND(24)
    x0 += ks2; x1 += 0u + 2u;
    TF_ROUND(13) TF_ROUND(15) TF_ROUND(26) TF_ROUND(6)
    x0 += 0u;  x1 += ks1 + 3u;
    TF_ROUND(17) TF_ROUND(29) TF_ROUND(16) TF_ROUND(24)
    x0 += ks1; x1 += ks2 + 4u;
    TF_ROUND(13) TF_ROUND(15) TF_ROUND(26) TF_ROUND(6)
    x0 += ks2;
#undef TF_ROUND
    return x0;
}

__device__ __forceinline__ float drop_one(float v, unsigned int i) {
    unsigned int bits = threefry_x0_k42(i);
    float u = __uint_as_float(0x3f800000u | (bits >> 9)) - 1.0f;
    return (u < 0.9f) ? (v * (1.0f / 0.9f)) : 0.0f;
}

// ---------------------------------------------------------------------------
// packed fp32x2 helpers
// ---------------------------------------------------------------------------
__device__ __forceinline__ unsigned long long pack_dup(float x) {
    unsigned long long r;
    asm("mov.b64 %0, {%1, %1};" : "=l"(r) : "f"(x));
    return r;
}
__device__ __forceinline__ void ffma2(unsigned long long& d,
                                      unsigned long long a,
                                      unsigned long long b) {
    asm("fma.rn.f32x2 %0, %1, %2, %0;" : "+l"(d) : "l"(a), "l"(b));
}
__device__ __forceinline__ float2 unpack2(unsigned long long p) {
    float lo, hi;
    asm("mov.b64 {%0, %1}, %2;" : "=f"(lo), "=f"(hi) : "l"(p));
    return make_float2(lo, hi);
}

// ---------------------------------------------------------------------------
// Kernel 0: fused fp16-embed prep + row histogram.
// ---------------------------------------------------------------------------
__global__ void prep_hist_kernel(const float* __restrict__ embed_w,
                                 const int* __restrict__ row, int N, int E) {
    int idx = blockIdx.x * blockDim.x + threadIdx.x;
    if (idx < N * 32) {
        float4 f = reinterpret_cast<const float4*>(embed_w)[idx];
        __half2 a = __floats2half2_rn(f.x, f.y);
        __half2 b = __floats2half2_rn(f.z, f.w);
        uint2 u;
        u.x = *reinterpret_cast<uint32_t*>(&a);
        u.y = *reinterpret_cast<uint32_t*>(&b);
        g_ehalf[idx] = u;
    }
    int e0 = idx * 4;
    if (e0 + 3 < E) {
        int4 r4 = reinterpret_cast<const int4*>(row)[idx];
        atomicAdd(&g_counts[r4.x], 1);
        atomicAdd(&g_counts[r4.y], 1);
        atomicAdd(&g_counts[r4.z], 1);
        atomicAdd(&g_counts[r4.w], 1);
    } else if (e0 < E) {
        for (int e = e0; e < E; e++) atomicAdd(&g_counts[row[e]], 1);
    }
}

// ---------------------------------------------------------------------------
// Kernel 1: single-pass decoupled-lookback scan (also re-zeros counts).
// ---------------------------------------------------------------------------
__global__ __launch_bounds__(1024)
void scan_lookback_kernel(int N, int E) {
    __shared__ int sh[1024];
    __shared__ int sh_prefix;
    const int b = blockIdx.x, t = threadIdx.x;
    const int i0 = b * SCAN_CHUNK + 2 * t;

    int c0 = (i0 < N)     ? g_counts[i0]     : 0;
    int c1 = (i0 + 1 < N) ? g_counts[i0 + 1] : 0;
    int pair = c0 + c1;
    sh[t] = pair;
    __syncthreads();
    for (int off = 1; off < 1024; off <<= 1) {
        int v = (t >= off) ? sh[t - off] : 0;
        __syncthreads();
        sh[t] += v;
        __syncthreads();
    }
    int chunk_total = sh[1023];
    int incl_pair   = sh[t];

    if (t == 0) {
        g_blk_agg[b] = chunk_total;
        __threadfence();
        g_blk_flag[b] = 1;
        int running = 0;
        for (int j = b - 1; j >= 0; j--) {
            int f;
            do { f = g_blk_flag[j]; } while (f == 0);
            __threadfence();
            if (f == 2) { running += g_blk_inc[j]; break; }
            running += g_blk_agg[j];
        }
        g_blk_inc[b] = running + chunk_total;
        __threadfence();
        g_blk_flag[b] = 2;
        sh_prefix = running;
    }
    __syncthreads();
    int excl = incl_pair - pair + sh_prefix;

    if (i0 < N)     { g_row_start[i0]     = excl;      g_cursor[i0]     = excl;      g_counts[i0]     = 0; }
    if (i0 + 1 < N) { g_row_start[i0 + 1] = excl + c0; g_cursor[i0 + 1] = excl + c0; g_counts[i0 + 1] = 0; }
    if (i0 == N - 1 || i0 + 1 == N - 1) g_row_start[N] = E;
}

// ---------------------------------------------------------------------------
// Kernel 2: scatter edges into CSR order; v stored as half2(v,v).
// Also resets lookback flags for the next graph replay.
// ---------------------------------------------------------------------------
__global__ void scatter_kernel(const int* __restrict__ row,
                               const int* __restrict__ col,
                               const float* __restrict__ vals, int E) {
    if (blockIdx.x == 0 && threadIdx.x < 64) g_blk_flag[threadIdx.x] = 0;
    int e = blockIdx.x * blockDim.x + threadIdx.x;
    if (e >= E) return;
    int r = row[e];
    int pos = atomicAdd(&g_cursor[r], 1);
    __half2 hh = __float2half2_rn(vals[e]);      // (v, v) in fp16
    int vb = *reinterpret_cast<int*>(&hh);
    g_edges[pos] = make_int2(col[e], vb);
}

// ---------------------------------------------------------------------------
// Kernel 3 (PROFILED at index 3): fused CSR SpMM + residual + dropout + e-copy.
// Per 8-edge batch: 8 broadcast edge loads + 8 fp16 gathers + 16 HFMA2 into
// fp16 group accumulators, flushed to fp32 per batch. No SHFL, no per-term F2F.
// ---------------------------------------------------------------------------
__global__ __launch_bounds__(256)
void spmm_csr_kernel(const float* __restrict__ embed_w,
                     float* __restrict__ out, int N) {
    int r = (blockIdx.x * blockDim.x + threadIdx.x) >> 5;
    if (r >= N) return;
    int lane = threadIdx.x & 31;

    float4 acc = reinterpret_cast<const float4*>(embed_w)[(size_t)r * 32 + lane];
    reinterpret_cast<float4*>(out)[(size_t)r * 64 + lane] = acc;

    int start = g_row_start[r];
    int end   = g_row_start[r + 1];
    const __half2 hzero = __float2half2_rn(0.0f);

    for (int base = start; base < end; base += 8) {
        int2 ed[8];
#pragma unroll
        for (int u = 0; u < 8; u++)
            ed[u] = g_edges[base + u];               // broadcast, padded array
        uint2 hv[8];
#pragma unroll
        for (int u = 0; u < 8; u++)
            hv[u] = g_ehalf[(size_t)ed[u].x * 32 + lane];
        __half2 a01 = hzero, a23 = hzero;
#pragma unroll
        for (int u = 0; u < 8; u++) {
            __half2 vv = (base + u < end)
                       ? *reinterpret_cast<__half2*>(&ed[u].y) : hzero;
            a01 = __hfma2(vv, *reinterpret_cast<__half2*>(&hv[u].x), a01);
            a23 = __hfma2(vv, *reinterpret_cast<__half2*>(&hv[u].y), a23);
        }
        float2 f01 = __half22float2(a01);
        float2 f23 = __half22float2(a23);
        acc.x += f01.x;
        acc.y += f01.y;
        acc.z += f23.x;
        acc.w += f23.y;
    }

    unsigned int i0 = (unsigned int)r * 128u + (unsigned int)lane * 4u;
    acc.x = drop_one(acc.x, i0 + 0u);
    acc.y = drop_one(acc.y, i0 + 1u);
    acc.z = drop_one(acc.z, i0 + 2u);
    acc.w = drop_one(acc.w, i0 + 3u);

    reinterpret_cast<float4*>(g_m1)[(size_t)r * 32 + lane] = acc;
}

// ---------------------------------------------------------------------------
// Kernel 4: GEMM (FFMA2): out[:, 128:256] = leaky_relu(m1 @ W^T + b)
// ---------------------------------------------------------------------------
#define KPAD 132

__global__ __launch_bounds__(256, 2)
void gemm_kernel(const float* __restrict__ W,
                 const float* __restrict__ bias,
                 float* __restrict__ out, int N) {
    __shared__ float As[32 * KPAD];   // [k][row]
    __shared__ float Ws[32 * KPAD];   // [k][outcol]
    const int t  = threadIdx.x;
    const int tx = t & 15;
    const int ty = t >> 4;
    const int brow = blockIdx.x * 128;

    unsigned long long acc2[8][4];
#pragma unroll
    for (int u = 0; u < 8; u++)
#pragma unroll
        for (int v = 0; v < 4; v++) acc2[u][v] = 0ull;

#pragma unroll 1
    for (int kk = 0; kk < 4; kk++) {
        if (kk) __syncthreads();
#pragma unroll
        for (int i = 0; i < 4; i++) {
            int idx = t + i * 256;
            int r   = idx >> 3;
            int c4  = (idx & 7) * 4;
            int gr  = brow + r;
            float4 av = make_float4(0.f, 0.f, 0.f, 0.f);
            if (gr < N)
                av = *reinterpret_cast<const float4*>(g_m1 + (size_t)gr * D + kk * 32 + c4);
            As[(c4 + 0) * KPAD + r] = av.x;
            As[(c4 + 1) * KPAD + r] = av.y;
            As[(c4 + 2) * KPAD + r] = av.z;
            As[(c4 + 3) * KPAD + r] = av.w;
            float4 wv = *reinterpret_cast<const float4*>(W + (size_t)r * D + kk * 32 + c4);
            Ws[(c4 + 0) * KPAD + r] = wv.x;
            Ws[(c4 + 1) * KPAD + r] = wv.y;
            Ws[(c4 + 2) * KPAD + r] = wv.z;
            Ws[(c4 + 3) * KPAD + r] = wv.w;
        }
        __syncthreads();
#pragma unroll
        for (int k = 0; k < 32; k++) {
            float4 aLo = *reinterpret_cast<const float4*>(&As[k * KPAD + ty * 4]);
            float4 aHi = *reinterpret_cast<const float4*>(&As[k * KPAD + ty * 4 + 64]);
            const unsigned long long* wp =
                reinterpret_cast<const unsigned long long*>(&Ws[k * KPAD]);
            unsigned long long w0 = wp[tx * 2];
            unsigned long long w1 = wp[tx * 2 + 1];
            unsigned long long w2 = wp[tx * 2 + 32];
            unsigned long long w3 = wp[tx * 2 + 33];
            float a[8] = {aLo.x, aLo.y, aLo.z, aLo.w, aHi.x, aHi.y, aHi.z, aHi.w};
#pragma unroll
            for (int u = 0; u < 8; u++) {
                unsigned long long aa = pack_dup(a[u]);
                ffma2(acc2[u][0], aa, w0);
                ffma2(acc2[u][1], aa, w1);
                ffma2(acc2[u][2], aa, w2);
                ffma2(acc2[u][3], aa, w3);
            }
        }
    }

    float bv[8];
#pragma unroll
    for (int v = 0; v < 4; v++) {
        bv[v]     = bias[tx * 4 + v];
        bv[v + 4] = bias[tx * 4 + 64 + v];
    }

#pragma unroll
    for (int u = 0; u < 8; u++) {
        int gr = brow + ((u < 4) ? (ty * 4 + u) : (ty * 4 + 64 + u - 4));
        if (gr >= N) continue;
        float* o = out + (size_t)gr * 256 + 128;
        float2 p0 = unpack2(acc2[u][0]);
        float2 p1 = unpack2(acc2[u][1]);
        float2 p2 = unpack2(acc2[u][2]);
        float2 p3 = unpack2(acc2[u][3]);
        float y[8] = {p0.x, p0.y, p1.x, p1.y, p2.x, p2.y, p3.x, p3.y};
#pragma unroll
        for (int v = 0; v < 8; v++) {
            float z = y[v] + bv[v];
            y[v] = (z >= 0.0f) ? z : 0.2f * z;
        }
        *reinterpret_cast<float4*>(o + tx * 4)      = make_float4(y[0], y[1], y[2], y[3]);
        *reinterpret_cast<float4*>(o + tx * 4 + 64) = make_float4(y[4], y[5], y[6], y[7]);
    }
}

// ---------------------------------------------------------------------------
extern "C" void kernel_launch(void* const* d_in, const int* in_sizes, int n_in,
                              void* d_out, int out_size) {
    const int*   row     = (const int*)d_in[1];
    const int*   col     = (const int*)d_in[2];
    const float* vals    = (const float*)d_in[3];
    const float* embed_w = (const float*)d_in[4];
    const float* fc_w    = (const float*)d_in[5];
    const float* fc_b    = (const float*)d_in[6];
    float* out = (float*)d_out;

    const int N = in_sizes[0];
    const int E = in_sizes[1];
    const int nchunks = (N + SCAN_CHUNK - 1) / SCAN_CHUNK;   // 49

    int prep_threads = N * 32;
    if ((E + 3) / 4 > prep_threads) prep_threads = (E + 3) / 4;

    // 0: fused fp16 prep + histogram
    prep_hist_kernel<<<(prep_threads + 255) / 256, 256>>>(embed_w, row, N, E);
    // 1: single-pass scan (also re-zeros counts)
    scan_lookback_kernel<<<nchunks, 1024>>>(N, E);
    // 2: scatter with half2-packed v (also resets lookback flags)
    scatter_kernel<<<(E + 255) / 256, 256>>>(row, col, vals, E);
    // 3: fused SpMM + residual + dropout + e-copy  <-- profiled launch index
    spmm_csr_kernel<<<(N * 32 + 255) / 256, 256>>>(embed_w, out, N);
    // 4: GEMM
    gemm_kernel<<<(N + 127) / 128, 256>>>(fc_w, fc_b, out, N);
}